// round 4
// baseline (speedup 1.0000x reference)
#include <cuda_runtime.h>
#include <math.h>

#define B_SZ 256
#define N_SZ 512
#define D_SZ 256
#define R_SZ 64

// Scratch (allocation-free: __device__ globals)
__device__ float g_p[B_SZ * D_SZ];   // p[b,d] = (tokns_k @ Wq^T @ Wk)[b,d]
__device__ float g_g[B_SZ * D_SZ];   // g[b,d] = sum_n alpha[b,n] * H[b,n,d]

// ---------------------------------------------------------------------------
// K1: p = (tokns_k @ Wq^T) @ Wk     (one CTA per batch row b)
// ---------------------------------------------------------------------------
__global__ void __launch_bounds__(256) k1_compute_p(
    const float* __restrict__ tok,   // [B, 256]
    const float* __restrict__ Wq,    // [64, 256]
    const float* __restrict__ Wk)    // [64, 256]
{
    __shared__ float t_s[D_SZ];
    __shared__ float q_s[R_SZ];
    const int b = blockIdx.x;
    const int tid = threadIdx.x;
    const int w = tid >> 5, l = tid & 31;

    t_s[tid] = tok[b * D_SZ + tid];
    __syncthreads();

    // q[b,r] = dot(tok[b], Wq[r])  — warp w handles rows r = w, w+8, ...
    for (int r = w; r < R_SZ; r += 8) {
        float partial = 0.f;
        #pragma unroll
        for (int i = 0; i < 8; i++)
            partial += Wq[r * D_SZ + l + 32 * i] * t_s[l + 32 * i];
        #pragma unroll
        for (int off = 16; off > 0; off >>= 1)
            partial += __shfl_xor_sync(0xffffffffu, partial, off);
        if (l == 0) q_s[r] = partial;
    }
    __syncthreads();

    // p[b,j] = sum_r q[b,r] * Wk[r,j]   (coalesced over j = tid)
    float acc = 0.f;
    #pragma unroll
    for (int r = 0; r < R_SZ; r++)
        acc += q_s[r] * Wk[r * D_SZ + tid];
    g_p[b * D_SZ + tid] = acc;
}

// ---------------------------------------------------------------------------
// K2: per-batch attention. Pass1: scores = H[b,n]·p[b] (masked, scaled) ->
// softmax -> write alpha. Pass2: g[b,t] = sum_n alpha[n] * H[b,n,t].
// ---------------------------------------------------------------------------
__global__ void __launch_bounds__(256) k2_attn(
    const float* __restrict__ H,          // [B, N, 256]
    const int* __restrict__ mask,         // [B, N] (bool -> int32; !=0 test also
                                          //  works if harness used float32)
    const float* __restrict__ log_scale,  // [1]
    float* __restrict__ alpha_out)        // [B, N]
{
    __shared__ __align__(16) float p_s[D_SZ];
    __shared__ float s_s[N_SZ];
    __shared__ float red_max[8];
    __shared__ float red_sum[8];

    const int b = blockIdx.x;
    const int tid = threadIdx.x;
    const int w = tid >> 5, l = tid & 31;

    p_s[tid] = g_p[b * D_SZ + tid];
    const float inv_scale = 1.f / fmaxf(expf(log_scale[0]), 0.1f);
    __syncthreads();

    const float* Hb = H + (size_t)b * N_SZ * D_SZ;

    // lane-private fragment of p (float4 at indices 4l and 128+4l)
    const float4* p4 = reinterpret_cast<const float4*>(p_s);
    const float4 pf0 = p4[l];
    const float4 pf1 = p4[l + 32];

    // Pass 1: warp w computes rows n ≡ w (mod 8); unroll 2 rows for MLP.
    for (int n0 = w; n0 < N_SZ; n0 += 16) {
        const int n1 = n0 + 8;
        const float4* h4a = reinterpret_cast<const float4*>(Hb + n0 * D_SZ);
        const float4* h4b = reinterpret_cast<const float4*>(Hb + n1 * D_SZ);
        float4 a0 = h4a[l], a1 = h4a[l + 32];
        float4 b0 = h4b[l], b1 = h4b[l + 32];

        float pa = a0.x * pf0.x + a0.y * pf0.y + a0.z * pf0.z + a0.w * pf0.w
                 + a1.x * pf1.x + a1.y * pf1.y + a1.z * pf1.z + a1.w * pf1.w;
        float pb = b0.x * pf0.x + b0.y * pf0.y + b0.z * pf0.z + b0.w * pf0.w
                 + b1.x * pf1.x + b1.y * pf1.y + b1.z * pf1.z + b1.w * pf1.w;

        #pragma unroll
        for (int off = 16; off > 0; off >>= 1) {
            pa += __shfl_xor_sync(0xffffffffu, pa, off);
            pb += __shfl_xor_sync(0xffffffffu, pb, off);
        }
        if (l == 0) {
            s_s[n0] = (mask[b * N_SZ + n0] != 0) ? pa * inv_scale : -INFINITY;
            s_s[n1] = (mask[b * N_SZ + n1] != 0) ? pb * inv_scale : -INFINITY;
        }
    }
    __syncthreads();

    // Block softmax over s_s[512]
    float v = fmaxf(s_s[tid], s_s[tid + 256]);
    #pragma unroll
    for (int off = 16; off > 0; off >>= 1)
        v = fmaxf(v, __shfl_xor_sync(0xffffffffu, v, off));
    if (l == 0) red_max[w] = v;
    __syncthreads();
    float m = red_max[0];
    #pragma unroll
    for (int i = 1; i < 8; i++) m = fmaxf(m, red_max[i]);

    float e0 = __expf(s_s[tid] - m);          // exp(-inf) = 0 for masked
    float e1 = __expf(s_s[tid + 256] - m);
    float sv = e0 + e1;
    #pragma unroll
    for (int off = 16; off > 0; off >>= 1)
        sv += __shfl_xor_sync(0xffffffffu, sv, off);
    if (l == 0) red_sum[w] = sv;
    __syncthreads();
    float sum = red_sum[0];
    #pragma unroll
    for (int i = 1; i < 8; i++) sum += red_sum[i];
    const float inv = 1.f / sum;

    const float a0n = e0 * inv;
    const float a1n = e1 * inv;
    alpha_out[b * N_SZ + tid] = a0n;
    alpha_out[b * N_SZ + tid + 256] = a1n;
    s_s[tid] = a0n;
    s_s[tid + 256] = a1n;
    __syncthreads();

    // Pass 2: g[b,t] = sum_n alpha[n] * H[b,n,t]  (coalesced over t = tid)
    float acc = 0.f;
    for (int n = 0; n < N_SZ; n += 8) {
        float h[8];
        #pragma unroll
        for (int j = 0; j < 8; j++)
            h[j] = Hb[(n + j) * D_SZ + tid];
        #pragma unroll
        for (int j = 0; j < 8; j++)
            acc += s_s[n + j] * h[j];
    }
    g_g[b * D_SZ + tid] = acc;
}

// ---------------------------------------------------------------------------
// K3: ctx[b,e] = sum_d g[b,d] * Wv[e,d]   (32x32 tiled NT GEMM)
// ---------------------------------------------------------------------------
__global__ void __launch_bounds__(256) k3_ctx(
    const float* __restrict__ Wv,    // [256, 256]
    float* __restrict__ ctx)         // [B, 256]
{
    __shared__ float Gs[32][33];
    __shared__ float Ws[32][33];
    const int e0 = blockIdx.x * 32;
    const int b0 = blockIdx.y * 32;
    const int tid = threadIdx.x;
    const int tx = tid & 31, ty = tid >> 5;  // 32 x 8 threads

    float acc[4] = {0.f, 0.f, 0.f, 0.f};

    for (int d0 = 0; d0 < D_SZ; d0 += 32) {
        #pragma unroll
        for (int r = 0; r < 4; r++) {
            const int row = ty + 8 * r;
            Gs[row][tx] = g_g[(b0 + row) * D_SZ + d0 + tx];
            Ws[row][tx] = Wv[(e0 + row) * D_SZ + d0 + tx];
        }
        __syncthreads();
        #pragma unroll
        for (int kk = 0; kk < 32; kk++) {
            const float wv = Ws[tx][kk];
            #pragma unroll
            for (int r = 0; r < 4; r++)
                acc[r] += Gs[ty + 8 * r][kk] * wv;
        }
        __syncthreads();
    }
    #pragma unroll
    for (int r = 0; r < 4; r++)
        ctx[(b0 + ty + 8 * r) * D_SZ + e0 + tx] = acc[r];
}

// ---------------------------------------------------------------------------
extern "C" void kernel_launch(void* const* d_in, const int* in_sizes, int n_in,
                              void* d_out, int out_size) {
    const float* tok  = (const float*)d_in[0];           // [256,256]
    const float* H    = (const float*)d_in[1];           // [256,512,256]
    const int* mask   = (const int*)d_in[2];             // [256,512] bool->int32
    const float* Wq   = (const float*)d_in[3];           // [64,256]
    const float* Wk   = (const float*)d_in[4];           // [64,256]
    const float* Wv   = (const float*)d_in[5];           // [256,256]
    const float* ls   = (const float*)d_in[6];           // [1]

    float* out_alpha = (float*)d_out;                    // [256,512]
    float* out_ctx   = out_alpha + B_SZ * N_SZ;          // [256,256]

    k1_compute_p<<<B_SZ, 256>>>(tok, Wq, Wk);
    k2_attn<<<B_SZ, 256>>>(H, mask, ls, out_alpha);
    k3_ctx<<<dim3(8, 8), 256>>>(Wv, out_ctx);
}

// round 5
// speedup vs baseline: 1.2176x; 1.2176x over previous
#include <cuda_runtime.h>
#include <math.h>

#define B_SZ 256
#define N_SZ 512
#define D_SZ 256
#define R_SZ 64

// Scratch (allocation-free: __device__ globals)
__device__ float g_M[D_SZ * D_SZ];   // M = Wq^T @ Wk                [256,256]
__device__ float g_p[B_SZ * D_SZ];   // p = tok @ M                  [256,256]
__device__ float g_s[B_SZ * N_SZ];   // raw scores H·p               [256,512]
__device__ float g_g[B_SZ * D_SZ];   // g[b,d] = sum_n alpha H       [256,256]

// ---------------------------------------------------------------------------
// kM: M[d,j] = sum_r Wq[r,d] * Wk[r,j]    (32x32 tiles, K=64)
// ---------------------------------------------------------------------------
__global__ void __launch_bounds__(256) kM_wqwk(
    const float* __restrict__ Wq,    // [64, 256]
    const float* __restrict__ Wk)    // [64, 256]
{
    __shared__ float A[32][33];      // A[kk][d] = Wq[k0+kk][d0+d]
    __shared__ float Bs[32][33];     // B[kk][j] = Wk[k0+kk][j0+j]
    const int d0 = blockIdx.y * 32;
    const int j0 = blockIdx.x * 32;
    const int tid = threadIdx.x;
    const int tx = tid & 31, ty = tid >> 5;   // 32 x 8

    float acc[4] = {0.f, 0.f, 0.f, 0.f};

    for (int k0 = 0; k0 < R_SZ; k0 += 32) {
        #pragma unroll
        for (int r = 0; r < 4; r++) {
            const int kk = ty + 8 * r;
            A[kk][tx]  = Wq[(k0 + kk) * D_SZ + d0 + tx];
            Bs[kk][tx] = Wk[(k0 + kk) * D_SZ + j0 + tx];
        }
        __syncthreads();
        #pragma unroll
        for (int kk = 0; kk < 32; kk++) {
            const float bv = Bs[kk][tx];
            #pragma unroll
            for (int r = 0; r < 4; r++)
                acc[r] += A[kk][ty + 8 * r] * bv;
        }
        __syncthreads();
    }
    #pragma unroll
    for (int r = 0; r < 4; r++)
        g_M[(d0 + ty + 8 * r) * D_SZ + j0 + tx] = acc[r];
}

// ---------------------------------------------------------------------------
// k1: p[b,j] = sum_d tok[b,d] * M[d,j]    (32x32 tiles, K=256)
// ---------------------------------------------------------------------------
__global__ void __launch_bounds__(256) k1_p(
    const float* __restrict__ tok)   // [256, 256]
{
    __shared__ float As[32][33];     // tok[b0+row][d0+kk]
    __shared__ float Bs[32][33];     // M[d0+kk][j0+j]
    const int j0 = blockIdx.x * 32;
    const int b0 = blockIdx.y * 32;
    const int tid = threadIdx.x;
    const int tx = tid & 31, ty = tid >> 5;

    float acc[4] = {0.f, 0.f, 0.f, 0.f};

    for (int d0 = 0; d0 < D_SZ; d0 += 32) {
        #pragma unroll
        for (int r = 0; r < 4; r++) {
            const int row = ty + 8 * r;
            As[row][tx] = tok[(b0 + row) * D_SZ + d0 + tx];
            Bs[row][tx] = g_M[(d0 + row) * D_SZ + j0 + tx];
        }
        __syncthreads();
        #pragma unroll
        for (int kk = 0; kk < 32; kk++) {
            const float bv = Bs[kk][tx];
            #pragma unroll
            for (int r = 0; r < 4; r++)
                acc[r] += As[ty + 8 * r][kk] * bv;
        }
        __syncthreads();
    }
    #pragma unroll
    for (int r = 0; r < 4; r++)
        g_p[(b0 + ty + 8 * r) * D_SZ + j0 + tx] = acc[r];
}

// ---------------------------------------------------------------------------
// K2a: raw scores s[b,n] = H[b,n,:]·p[b,:]     grid (8 ntiles, 256 b)
// ---------------------------------------------------------------------------
__global__ void __launch_bounds__(256) k2a_scores(
    const float* __restrict__ H)          // [B, N, 256]
{
    __shared__ __align__(16) float p_s[D_SZ];
    const int b = blockIdx.y;
    const int n0 = blockIdx.x * 64;
    const int tid = threadIdx.x;
    const int w = tid >> 5, l = tid & 31;

    p_s[tid] = g_p[b * D_SZ + tid];
    __syncthreads();

    const float* Hb = H + (size_t)b * N_SZ * D_SZ;
    const float4* p4 = reinterpret_cast<const float4*>(p_s);
    const float4 pf0 = p4[l];
    const float4 pf1 = p4[l + 32];

    // warp w handles rows n0 + w + 8*i, i = 0..7; unroll 2 rows for MLP
    #pragma unroll
    for (int i = 0; i < 8; i += 2) {
        const int na = n0 + w + 8 * i;
        const int nb = na + 8;
        const float4* h4a = reinterpret_cast<const float4*>(Hb + na * D_SZ);
        const float4* h4b = reinterpret_cast<const float4*>(Hb + nb * D_SZ);
        float4 a0 = h4a[l], a1 = h4a[l + 32];
        float4 b0 = h4b[l], b1 = h4b[l + 32];

        float pa = a0.x * pf0.x + a0.y * pf0.y + a0.z * pf0.z + a0.w * pf0.w
                 + a1.x * pf1.x + a1.y * pf1.y + a1.z * pf1.z + a1.w * pf1.w;
        float pb = b0.x * pf0.x + b0.y * pf0.y + b0.z * pf0.z + b0.w * pf0.w
                 + b1.x * pf1.x + b1.y * pf1.y + b1.z * pf1.z + b1.w * pf1.w;

        #pragma unroll
        for (int off = 16; off > 0; off >>= 1) {
            pa += __shfl_xor_sync(0xffffffffu, pa, off);
            pb += __shfl_xor_sync(0xffffffffu, pb, off);
        }
        if (l == 0) {
            g_s[b * N_SZ + na] = pa;
            g_s[b * N_SZ + nb] = pb;
        }
    }
}

// ---------------------------------------------------------------------------
// K2b: softmax over n (scale + mask), writes alpha, zeroes g_g.  grid 256
// ---------------------------------------------------------------------------
__global__ void __launch_bounds__(256) k2b_softmax(
    const int* __restrict__ mask,         // [B, N] bool->int32
    const float* __restrict__ log_scale,  // [1]
    float* __restrict__ alpha_out)        // [B, N]
{
    __shared__ float red_max[8];
    __shared__ float red_sum[8];
    const int b = blockIdx.x;
    const int tid = threadIdx.x;
    const int w = tid >> 5, l = tid & 31;

    const float inv_scale = 1.f / fmaxf(expf(log_scale[0]), 0.1f);

    float s0 = (mask[b * N_SZ + tid] != 0)
               ? g_s[b * N_SZ + tid] * inv_scale : -INFINITY;
    float s1 = (mask[b * N_SZ + tid + 256] != 0)
               ? g_s[b * N_SZ + tid + 256] * inv_scale : -INFINITY;

    float v = fmaxf(s0, s1);
    #pragma unroll
    for (int off = 16; off > 0; off >>= 1)
        v = fmaxf(v, __shfl_xor_sync(0xffffffffu, v, off));
    if (l == 0) red_max[w] = v;
    __syncthreads();
    float m = red_max[0];
    #pragma unroll
    for (int i = 1; i < 8; i++) m = fmaxf(m, red_max[i]);

    float e0 = __expf(s0 - m);
    float e1 = __expf(s1 - m);
    float sv = e0 + e1;
    #pragma unroll
    for (int off = 16; off > 0; off >>= 1)
        sv += __shfl_xor_sync(0xffffffffu, sv, off);
    if (l == 0) red_sum[w] = sv;
    __syncthreads();
    float sum = red_sum[0];
    #pragma unroll
    for (int i = 1; i < 8; i++) sum += red_sum[i];
    const float inv = 1.f / sum;

    alpha_out[b * N_SZ + tid]       = e0 * inv;
    alpha_out[b * N_SZ + tid + 256] = e1 * inv;
    g_g[b * D_SZ + tid] = 0.f;    // zero accumulator for K2c
}

// ---------------------------------------------------------------------------
// K2c: g[b,d] += sum_{n in tile} alpha[b,n] * H[b,n,d]   grid (8, 256)
// ---------------------------------------------------------------------------
__global__ void __launch_bounds__(256) k2c_g(
    const float* __restrict__ H,
    const float* __restrict__ alpha)      // [B, N] (= d_out alpha region)
{
    __shared__ float a_s[64];
    const int b = blockIdx.y;
    const int n0 = blockIdx.x * 64;
    const int tid = threadIdx.x;

    if (tid < 64) a_s[tid] = alpha[b * N_SZ + n0 + tid];
    __syncthreads();

    const float* Hb = H + (size_t)b * N_SZ * D_SZ + (size_t)n0 * D_SZ;

    float acc = 0.f;
    #pragma unroll 8
    for (int j = 0; j < 64; j++)
        acc += a_s[j] * Hb[j * D_SZ + tid];

    atomicAdd(&g_g[b * D_SZ + tid], acc);
}

// ---------------------------------------------------------------------------
// K3: ctx[b,e] = sum_d g[b,d] * Wv[e,d]   (32x32 tiled NT GEMM)
// ---------------------------------------------------------------------------
__global__ void __launch_bounds__(256) k3_ctx(
    const float* __restrict__ Wv,    // [256, 256]
    float* __restrict__ ctx)         // [B, 256]
{
    __shared__ float Gs[32][33];
    __shared__ float Ws[32][33];
    const int e0 = blockIdx.x * 32;
    const int b0 = blockIdx.y * 32;
    const int tid = threadIdx.x;
    const int tx = tid & 31, ty = tid >> 5;

    float acc[4] = {0.f, 0.f, 0.f, 0.f};

    for (int d0 = 0; d0 < D_SZ; d0 += 32) {
        #pragma unroll
        for (int r = 0; r < 4; r++) {
            const int row = ty + 8 * r;
            Gs[row][tx] = g_g[(b0 + row) * D_SZ + d0 + tx];
            Ws[row][tx] = Wv[(e0 + row) * D_SZ + d0 + tx];
        }
        __syncthreads();
        #pragma unroll
        for (int kk = 0; kk < 32; kk++) {
            const float wv = Ws[tx][kk];
            #pragma unroll
            for (int r = 0; r < 4; r++)
                acc[r] += Gs[ty + 8 * r][kk] * wv;
        }
        __syncthreads();
    }
    #pragma unroll
    for (int r = 0; r < 4; r++)
        ctx[(b0 + ty + 8 * r) * D_SZ + e0 + tx] = acc[r];
}

// ---------------------------------------------------------------------------
extern "C" void kernel_launch(void* const* d_in, const int* in_sizes, int n_in,
                              void* d_out, int out_size) {
    const float* tok  = (const float*)d_in[0];           // [256,256]
    const float* H    = (const float*)d_in[1];           // [256,512,256]
    const int* mask   = (const int*)d_in[2];             // [256,512] bool->int32
    const float* Wq   = (const float*)d_in[3];           // [64,256]
    const float* Wk   = (const float*)d_in[4];           // [64,256]
    const float* Wv   = (const float*)d_in[5];           // [256,256]
    const float* ls   = (const float*)d_in[6];           // [1]

    float* out_alpha = (float*)d_out;                    // [256,512]
    float* out_ctx   = out_alpha + B_SZ * N_SZ;          // [256,256]

    kM_wqwk<<<dim3(8, 8), 256>>>(Wq, Wk);
    k1_p<<<dim3(8, 8), 256>>>(tok);
    k2a_scores<<<dim3(8, B_SZ), 256>>>(H);
    k2b_softmax<<<B_SZ, 256>>>(mask, ls, out_alpha);
    k2c_g<<<dim3(8, B_SZ), 256>>>(H, out_alpha);
    k3_ctx<<<dim3(8, 8), 256>>>(Wv, out_ctx);
}

// round 6
// speedup vs baseline: 1.2421x; 1.0201x over previous
#include <cuda_runtime.h>
#include <math.h>

#define B_SZ 256
#define N_SZ 512
#define D_SZ 256
#define R_SZ 64
#define NT   8          // n-tiles per batch
#define TN   64         // rows per n-tile

// Scratch (allocation-free: __device__ globals)
__device__ float g_M[D_SZ * D_SZ];          // M = Wq^T @ Wk
__device__ float g_p[B_SZ * D_SZ];          // p = tok @ M
__device__ float g_s[B_SZ * N_SZ];          // masked+scaled scores
__device__ float g_mt[B_SZ * NT];           // tile max
__device__ float g_zt[B_SZ * NT];           // tile sum of exp
__device__ float g_part[B_SZ * NT * D_SZ];  // unnormalized partial g
__device__ float g_g[B_SZ * D_SZ];          // final weighted sum

// ---------------------------------------------------------------------------
// kM: M[d,j] = sum_r Wq[r,d] * Wk[r,j]    (32x32 tiles, K=64)
// ---------------------------------------------------------------------------
__global__ void __launch_bounds__(256) kM_wqwk(
    const float* __restrict__ Wq, const float* __restrict__ Wk)
{
    __shared__ float A[32][33];
    __shared__ float Bs[32][33];
    const int d0 = blockIdx.y * 32, j0 = blockIdx.x * 32;
    const int tid = threadIdx.x, tx = tid & 31, ty = tid >> 5;
    float acc[4] = {0.f, 0.f, 0.f, 0.f};

    for (int k0 = 0; k0 < R_SZ; k0 += 32) {
        #pragma unroll
        for (int r = 0; r < 4; r++) {
            const int kk = ty + 8 * r;
            A[kk][tx]  = Wq[(k0 + kk) * D_SZ + d0 + tx];
            Bs[kk][tx] = Wk[(k0 + kk) * D_SZ + j0 + tx];
        }
        __syncthreads();
        #pragma unroll
        for (int kk = 0; kk < 32; kk++) {
            const float bv = Bs[kk][tx];
            #pragma unroll
            for (int r = 0; r < 4; r++)
                acc[r] += A[kk][ty + 8 * r] * bv;
        }
        __syncthreads();
    }
    #pragma unroll
    for (int r = 0; r < 4; r++)
        g_M[(d0 + ty + 8 * r) * D_SZ + j0 + tx] = acc[r];
}

// ---------------------------------------------------------------------------
// k1: p[b,j] = sum_d tok[b,d] * M[d,j]
// ---------------------------------------------------------------------------
__global__ void __launch_bounds__(256) k1_p(const float* __restrict__ tok)
{
    __shared__ float As[32][33];
    __shared__ float Bs[32][33];
    const int j0 = blockIdx.x * 32, b0 = blockIdx.y * 32;
    const int tid = threadIdx.x, tx = tid & 31, ty = tid >> 5;
    float acc[4] = {0.f, 0.f, 0.f, 0.f};

    for (int d0 = 0; d0 < D_SZ; d0 += 32) {
        #pragma unroll
        for (int r = 0; r < 4; r++) {
            const int row = ty + 8 * r;
            As[row][tx] = tok[(b0 + row) * D_SZ + d0 + tx];
            Bs[row][tx] = g_M[(d0 + row) * D_SZ + j0 + tx];
        }
        __syncthreads();
        #pragma unroll
        for (int kk = 0; kk < 32; kk++) {
            const float bv = Bs[kk][tx];
            #pragma unroll
            for (int r = 0; r < 4; r++)
                acc[r] += As[ty + 8 * r][kk] * bv;
        }
        __syncthreads();
    }
    #pragma unroll
    for (int r = 0; r < 4; r++)
        g_p[(b0 + ty + 8 * r) * D_SZ + j0 + tx] = acc[r];
}

// ---------------------------------------------------------------------------
// K2a: single H pass. Per (tile t, batch b): stage 64x256 H tile in smem,
// scores -> tile-local softmax stats -> unnormalized partial g accumulation.
// ---------------------------------------------------------------------------
extern __shared__ float sm_Ht[];   // [TN * D_SZ] = 64 KB dynamic

__global__ void __launch_bounds__(256) k2a_pass(
    const float* __restrict__ H,
    const int* __restrict__ mask,
    const float* __restrict__ log_scale)
{
    __shared__ __align__(16) float p_s[D_SZ];
    __shared__ float s_s[TN];
    __shared__ float w_s[TN];

    const int b = blockIdx.y;
    const int t = blockIdx.x;
    const int n0 = t * TN;
    const int tid = threadIdx.x;
    const int w = tid >> 5, l = tid & 31;

    p_s[tid] = g_p[b * D_SZ + tid];
    const float inv_scale = 1.f / fmaxf(__expf(log_scale[0]), 0.1f);

    // Stage H tile: 64 rows x 256 cols, float4 coalesced
    const float* Hb = H + (size_t)b * N_SZ * D_SZ + (size_t)n0 * D_SZ;
    {
        const float4* src = reinterpret_cast<const float4*>(Hb);
        float4* dst = reinterpret_cast<float4*>(sm_Ht);
        #pragma unroll
        for (int j = 0; j < (TN * D_SZ / 4) / 256; j++)   // 16 iters
            dst[tid + 256 * j] = src[tid + 256 * j];
    }
    __syncthreads();

    // Scores: warp w handles rows n = w + 8*i
    const float4* p4 = reinterpret_cast<const float4*>(p_s);
    const float4 pf0 = p4[l];
    const float4 pf1 = p4[l + 32];

    #pragma unroll
    for (int i = 0; i < 8; i++) {
        const int n = w + 8 * i;
        const float4* h4 = reinterpret_cast<const float4*>(sm_Ht + n * D_SZ);
        float4 a0 = h4[l], a1 = h4[l + 32];
        float d = a0.x * pf0.x + a0.y * pf0.y + a0.z * pf0.z + a0.w * pf0.w
                + a1.x * pf1.x + a1.y * pf1.y + a1.z * pf1.z + a1.w * pf1.w;
        #pragma unroll
        for (int off = 16; off > 0; off >>= 1)
            d += __shfl_xor_sync(0xffffffffu, d, off);
        if (l == 0) {
            float s = (mask[b * N_SZ + n0 + n] != 0) ? d * inv_scale : -INFINITY;
            s_s[n] = s;
            g_s[b * N_SZ + n0 + n] = s;
        }
    }
    __syncthreads();

    // Tile-local softmax stats (warp 0): m_t, Z_t, weights w_s
    if (w == 0) {
        float v0 = s_s[l], v1 = s_s[l + 32];
        float v = fmaxf(v0, v1);
        #pragma unroll
        for (int off = 16; off > 0; off >>= 1)
            v = fmaxf(v, __shfl_xor_sync(0xffffffffu, v, off));
        const float m_t = v;                               // may be -inf
        const float mu = (m_t == -INFINITY) ? 0.f : m_t;   // NaN guard
        const float w0 = __expf(v0 - mu);                  // exp(-inf)=0
        const float w1 = __expf(v1 - mu);
        w_s[l] = w0;
        w_s[l + 32] = w1;
        float z = w0 + w1;
        #pragma unroll
        for (int off = 16; off > 0; off >>= 1)
            z += __shfl_xor_sync(0xffffffffu, z, off);
        if (l == 0) {
            g_mt[b * NT + t] = m_t;
            g_zt[b * NT + t] = z;
        }
    }
    __syncthreads();

    // Partial g: thread tid owns column d = tid
    float acc = 0.f;
    #pragma unroll 8
    for (int n = 0; n < TN; n++)
        acc += w_s[n] * sm_Ht[n * D_SZ + tid];
    g_part[(b * NT + t) * D_SZ + tid] = acc;
}

// ---------------------------------------------------------------------------
// K2b: combine tile stats -> exact alpha + final g.  grid 256 (b), block 256
// ---------------------------------------------------------------------------
__global__ void __launch_bounds__(256) k2b_combine(
    float* __restrict__ alpha_out)
{
    __shared__ float f_s[NT];
    __shared__ float sm_M, sm_invZ;
    const int b = blockIdx.x;
    const int tid = threadIdx.x;

    if (tid < 32) {
        const float m_t = (tid < NT) ? g_mt[b * NT + tid] : -INFINITY;
        const float z_t = (tid < NT) ? g_zt[b * NT + tid] : 0.f;
        float M = m_t;
        #pragma unroll
        for (int off = 16; off > 0; off >>= 1)
            M = fmaxf(M, __shfl_xor_sync(0xffffffffu, M, off));
        const float e = (m_t == -INFINITY) ? 0.f : __expf(m_t - M);
        float Z = z_t * e;
        #pragma unroll
        for (int off = 16; off > 0; off >>= 1)
            Z += __shfl_xor_sync(0xffffffffu, Z, off);
        const float invZ = 1.f / Z;
        if (tid < NT) f_s[tid] = e * invZ;
        if (tid == 0) { sm_M = M; sm_invZ = invZ; }
    }
    __syncthreads();

    const float M = sm_M, invZ = sm_invZ;

    // exact alpha from stored scores (exp(-inf - M) = 0 for masked)
    alpha_out[b * N_SZ + tid] = __expf(g_s[b * N_SZ + tid] - M) * invZ;
    alpha_out[b * N_SZ + tid + 256] =
        __expf(g_s[b * N_SZ + tid + 256] - M) * invZ;

    // g[b,d] = sum_t f_t * g_part[b,t,d]
    float acc = 0.f;
    #pragma unroll
    for (int t = 0; t < NT; t++)
        acc += f_s[t] * g_part[(b * NT + t) * D_SZ + tid];
    g_g[b * D_SZ + tid] = acc;
}

// ---------------------------------------------------------------------------
// K3: ctx[b,e] = sum_d g[b,d] * Wv[e,d]   (32x32 tiled NT GEMM)
// ---------------------------------------------------------------------------
__global__ void __launch_bounds__(256) k3_ctx(
    const float* __restrict__ Wv, float* __restrict__ ctx)
{
    __shared__ float Gs[32][33];
    __shared__ float Ws[32][33];
    const int e0 = blockIdx.x * 32, b0 = blockIdx.y * 32;
    const int tid = threadIdx.x, tx = tid & 31, ty = tid >> 5;
    float acc[4] = {0.f, 0.f, 0.f, 0.f};

    for (int d0 = 0; d0 < D_SZ; d0 += 32) {
        #pragma unroll
        for (int r = 0; r < 4; r++) {
            const int row = ty + 8 * r;
            Gs[row][tx] = g_g[(b0 + row) * D_SZ + d0 + tx];
            Ws[row][tx] = Wv[(e0 + row) * D_SZ + d0 + tx];
        }
        __syncthreads();
        #pragma unroll
        for (int kk = 0; kk < 32; kk++) {
            const float wv = Ws[tx][kk];
            #pragma unroll
            for (int r = 0; r < 4; r++)
                acc[r] += Gs[ty + 8 * r][kk] * wv;
        }
        __syncthreads();
    }
    #pragma unroll
    for (int r = 0; r < 4; r++)
        ctx[(b0 + ty + 8 * r) * D_SZ + e0 + tx] = acc[r];
}

// ---------------------------------------------------------------------------
extern "C" void kernel_launch(void* const* d_in, const int* in_sizes, int n_in,
                              void* d_out, int out_size) {
    const float* tok  = (const float*)d_in[0];
    const float* H    = (const float*)d_in[1];
    const int* mask   = (const int*)d_in[2];
    const float* Wq   = (const float*)d_in[3];
    const float* Wk   = (const float*)d_in[4];
    const float* Wv   = (const float*)d_in[5];
    const float* ls   = (const float*)d_in[6];

    float* out_alpha = (float*)d_out;                 // [256,512]
    float* out_ctx   = out_alpha + B_SZ * N_SZ;       // [256,256]

    const int dyn_smem = TN * D_SZ * sizeof(float);   // 64 KB
    cudaFuncSetAttribute(k2a_pass,
                         cudaFuncAttributeMaxDynamicSharedMemorySize, dyn_smem);

    kM_wqwk<<<dim3(8, 8), 256>>>(Wq, Wk);
    k1_p<<<dim3(8, 8), 256>>>(tok);
    k2a_pass<<<dim3(NT, B_SZ), 256, dyn_smem>>>(H, mask, ls);
    k2b_combine<<<B_SZ, 256>>>(out_alpha);
    k3_ctx<<<dim3(8, 8), 256>>>(Wv, out_ctx);
}